// round 3
// baseline (speedup 1.0000x reference)
#include <cuda_runtime.h>

#define N_NODES 50000
#define N_EDGES 800000
#define F_IN    256
#define HDIM    128

// Scratch (device globals: no allocation allowed in kernel_launch)
__device__ float g_buf0[N_NODES * HDIM];
__device__ float g_buf1[N_NODES * HDIM];
__device__ int   g_deg[N_NODES];
__device__ float g_dinv[N_NODES];

// ---------------------------------------------------------------- degree
__global__ void zero_deg_kernel() {
    int i = blockIdx.x * blockDim.x + threadIdx.x;
    if (i < N_NODES) g_deg[i] = 0;
}

__global__ void count_deg_kernel(const int* __restrict__ dst) {
    int i = blockIdx.x * blockDim.x + threadIdx.x;
    if (i < N_EDGES) atomicAdd(&g_deg[dst[i]], 1);
}

__global__ void compute_dinv_kernel() {
    int i = blockIdx.x * blockDim.x + threadIdx.x;
    if (i < N_NODES) g_dinv[i] = rsqrtf((float)(g_deg[i] + 1));
}

// ---------------------------------------------------------------- SGEMM
// C[M,128] = A[M,K] @ B[K,128], row-major, fp32.
// BM=128, BN=128 (full width), BK=8, 256 threads, 8x8 register tile.
__global__ void __launch_bounds__(256) sgemm_n128(
    const float* __restrict__ A, const float* __restrict__ B,
    float* __restrict__ C, int M, int K)
{
    const int N = 128;
    __shared__ float As[8][128];
    __shared__ float Bs[8][128];

    int tid = threadIdx.x;
    int bm  = blockIdx.x * 128;

    int tr = (tid >> 4) << 3;   // 0..120 step 8
    int tc = (tid & 15) << 3;   // 0..120 step 8

    int arow = tid >> 1;            // 0..127
    int acol = (tid & 1) << 2;      // 0 or 4
    int brow = tid >> 5;            // 0..7
    int bcol = (tid & 31) << 2;     // 0..124 step 4

    bool avalid = (bm + arow) < M;

    float acc[8][8];
#pragma unroll
    for (int i = 0; i < 8; i++)
#pragma unroll
        for (int j = 0; j < 8; j++) acc[i][j] = 0.0f;

    for (int k0 = 0; k0 < K; k0 += 8) {
        float4 av = make_float4(0.f, 0.f, 0.f, 0.f);
        if (avalid)
            av = *(const float4*)(A + (size_t)(bm + arow) * K + k0 + acol);
        As[acol + 0][arow] = av.x;
        As[acol + 1][arow] = av.y;
        As[acol + 2][arow] = av.z;
        As[acol + 3][arow] = av.w;

        *(float4*)&Bs[brow][bcol] =
            *(const float4*)(B + (size_t)(k0 + brow) * N + bcol);

        __syncthreads();

#pragma unroll
        for (int kk = 0; kk < 8; kk++) {
            float4 a0 = *(float4*)&As[kk][tr];
            float4 a1 = *(float4*)&As[kk][tr + 4];
            float4 b0 = *(float4*)&Bs[kk][tc];
            float4 b1 = *(float4*)&Bs[kk][tc + 4];
            float ar[8] = {a0.x, a0.y, a0.z, a0.w, a1.x, a1.y, a1.z, a1.w};
            float br[8] = {b0.x, b0.y, b0.z, b0.w, b1.x, b1.y, b1.z, b1.w};
#pragma unroll
            for (int i = 0; i < 8; i++)
#pragma unroll
                for (int j = 0; j < 8; j++)
                    acc[i][j] += ar[i] * br[j];
        }
        __syncthreads();
    }

#pragma unroll
    for (int i = 0; i < 8; i++) {
        int r = bm + tr + i;
        if (r < M) {
            *(float4*)(C + (size_t)r * N + tc) =
                make_float4(acc[i][0], acc[i][1], acc[i][2], acc[i][3]);
            *(float4*)(C + (size_t)r * N + tc + 4) =
                make_float4(acc[i][4], acc[i][5], acc[i][6], acc[i][7]);
        }
    }
}

// ---------------------------------------------------------------- aggregation
// agg[i,:] = h[i,:] * dinv[i]^2   (self-loop term, full write = no memset)
__global__ void self_init_kernel(const float4* __restrict__ h,
                                 float4* __restrict__ agg)
{
    int idx = blockIdx.x * blockDim.x + threadIdx.x;   // over N_NODES*32
    if (idx < N_NODES * 32) {
        int node = idx >> 5;
        float w = g_dinv[node];
        w = w * w;
        float4 v = h[idx];
        agg[idx] = make_float4(v.x * w, v.y * w, v.z * w, v.w * w);
    }
}

// One warp per edge: agg[d,:] += h[s,:] * dinv[s]*dinv[d]
__global__ void scatter_edges_kernel(const float4* __restrict__ h,
                                     float* __restrict__ agg,
                                     const int* __restrict__ src,
                                     const int* __restrict__ dst)
{
    int w = (blockIdx.x * blockDim.x + threadIdx.x) >> 5;
    if (w >= N_EDGES) return;
    int lane = threadIdx.x & 31;
    int s = __ldg(src + w);
    int d = __ldg(dst + w);
    float norm = g_dinv[s] * g_dinv[d];
    float4 v = __ldg(h + (size_t)s * 32 + lane);
    float* o = agg + (size_t)d * 128 + lane * 4;
    atomicAdd(o + 0, v.x * norm);
    atomicAdd(o + 1, v.y * norm);
    atomicAdd(o + 2, v.z * norm);
    atomicAdd(o + 3, v.w * norm);
}

// out[i] = relu(agg[i] + b[col])
__global__ void bias_relu_kernel(const float4* __restrict__ agg,
                                 float4* __restrict__ out,
                                 const float* __restrict__ b)
{
    int idx = blockIdx.x * blockDim.x + threadIdx.x;
    if (idx < N_NODES * 32) {
        int c = (idx & 31) << 2;
        float4 v = agg[idx];
        v.x = fmaxf(v.x + __ldg(b + c + 0), 0.f);
        v.y = fmaxf(v.y + __ldg(b + c + 1), 0.f);
        v.z = fmaxf(v.z + __ldg(b + c + 2), 0.f);
        v.w = fmaxf(v.w + __ldg(b + c + 3), 0.f);
        out[idx] = v;
    }
}

// ---------------------------------------------------------------- epilogue
// h = agg2 + b2 (written to out); out1 = h@Wh1+bh1; out2 = h@Wh2+bh2.
// One warp per node.
__global__ void finalize_kernel(const float4* __restrict__ agg,
                                const float* __restrict__ b2,
                                const float* __restrict__ Wh1,
                                const float* __restrict__ bh1,
                                const float* __restrict__ Wh2,
                                const float* __restrict__ bh2,
                                float* __restrict__ out1,
                                float* __restrict__ out2,
                                float4* __restrict__ outh)
{
    int w = (blockIdx.x * blockDim.x + threadIdx.x) >> 5;
    if (w >= N_NODES) return;
    int lane = threadIdx.x & 31;
    int c = lane << 2;

    float4 v = agg[(size_t)w * 32 + lane];
    v.x += __ldg(b2 + c + 0);
    v.y += __ldg(b2 + c + 1);
    v.z += __ldg(b2 + c + 2);
    v.w += __ldg(b2 + c + 3);
    outh[(size_t)w * 32 + lane] = v;

    float p[7];
#pragma unroll
    for (int j = 0; j < 4; j++) {
        p[j] = v.x * __ldg(Wh1 + (c + 0) * 4 + j)
             + v.y * __ldg(Wh1 + (c + 1) * 4 + j)
             + v.z * __ldg(Wh1 + (c + 2) * 4 + j)
             + v.w * __ldg(Wh1 + (c + 3) * 4 + j);
    }
#pragma unroll
    for (int j = 0; j < 3; j++) {
        p[4 + j] = v.x * __ldg(Wh2 + (c + 0) * 3 + j)
                 + v.y * __ldg(Wh2 + (c + 1) * 3 + j)
                 + v.z * __ldg(Wh2 + (c + 2) * 3 + j)
                 + v.w * __ldg(Wh2 + (c + 3) * 3 + j);
    }
#pragma unroll
    for (int j = 0; j < 7; j++) {
#pragma unroll
        for (int off = 16; off > 0; off >>= 1)
            p[j] += __shfl_xor_sync(0xffffffffu, p[j], off);
    }
    if (lane == 0) {
#pragma unroll
        for (int j = 0; j < 4; j++) out1[(size_t)w * 4 + j] = p[j] + __ldg(bh1 + j);
#pragma unroll
        for (int j = 0; j < 3; j++) out2[(size_t)w * 3 + j] = p[4 + j] + __ldg(bh2 + j);
    }
}

// ---------------------------------------------------------------- launch
extern "C" void kernel_launch(void* const* d_in, const int* in_sizes, int n_in,
                              void* d_out, int out_size)
{
    const float* x   = (const float*)d_in[0];
    const int*   ei  = (const int*)d_in[1];        // [2, E]
    const float* W1  = (const float*)d_in[2];
    const float* b1  = (const float*)d_in[3];
    const float* W2  = (const float*)d_in[4];
    const float* b2  = (const float*)d_in[5];
    const float* Wh1 = (const float*)d_in[6];
    const float* bh1 = (const float*)d_in[7];
    const float* Wh2 = (const float*)d_in[8];
    const float* bh2 = (const float*)d_in[9];

    const int* src = ei;
    const int* dst = ei + N_EDGES;

    float* out  = (float*)d_out;
    float* out1 = out;                               // [N, 4]
    float* out2 = out + (size_t)N_NODES * 4;         // [N, 3]
    float4* outh = (float4*)(out + (size_t)N_NODES * 7); // [N, 128]

    float* B0;  cudaGetSymbolAddress((void**)&B0, g_buf0);
    float* B1;  cudaGetSymbolAddress((void**)&B1, g_buf1);

    const int T = 256;
    int gNodes   = (N_NODES + T - 1) / T;
    int gEdges   = (N_EDGES + T - 1) / T;
    int gVec     = (N_NODES * 32 + T - 1) / T;       // float4-per-thread grids
    int gWarpE   = (N_EDGES * 32 + T - 1) / T;       // warp-per-edge
    int gWarpN   = (N_NODES * 32 + T - 1) / T;       // warp-per-node
    int gGemm    = (N_NODES + 127) / 128;

    // Normalization
    zero_deg_kernel<<<gNodes, T>>>();
    count_deg_kernel<<<gEdges, T>>>(dst);
    compute_dinv_kernel<<<gNodes, T>>>();

    // Layer 1: h1 = x @ W1 -> B0
    sgemm_n128<<<gGemm, T>>>(x, W1, B0, N_NODES, F_IN);
    // agg1 -> B1
    self_init_kernel<<<gVec, T>>>((const float4*)B0, (float4*)B1);
    scatter_edges_kernel<<<gWarpE, T>>>((const float4*)B0, B1, src, dst);
    // h1r = relu(agg1 + b1) -> B0
    bias_relu_kernel<<<gVec, T>>>((const float4*)B1, (float4*)B0, b1);

    // Layer 2: h2 = h1r @ W2 -> B1
    sgemm_n128<<<gGemm, T>>>(B0, W2, B1, N_NODES, HDIM);
    // agg2 -> B0
    self_init_kernel<<<gVec, T>>>((const float4*)B1, (float4*)B0);
    scatter_edges_kernel<<<gWarpE, T>>>((const float4*)B1, B0, src, dst);

    // Epilogue: h = agg2 + b2, heads
    finalize_kernel<<<gWarpN, T>>>((const float4*)B0, b2, Wh1, bh1, Wh2, bh2,
                                   out1, out2, outh);

    (void)in_sizes; (void)n_in; (void)out_size;
}

// round 4
// speedup vs baseline: 1.9616x; 1.9616x over previous
#include <cuda_runtime.h>

#define N_NODES 50000
#define N_EDGES 800000
#define F_IN    256
#define HDIM    128

// Scratch (device globals: no allocation allowed in kernel_launch)
__device__ float g_buf0[N_NODES * HDIM];
__device__ float g_buf1[N_NODES * HDIM];
__device__ int   g_deg[N_NODES];
__device__ int   g_rowptr[N_NODES];
__device__ int   g_cursor[N_NODES];
__device__ int   g_csrsrc[N_EDGES];
__device__ float g_dinv[N_NODES];

// ---------------------------------------------------------------- degree
__global__ void zero_kernel() {
    int i = blockIdx.x * blockDim.x + threadIdx.x;
    if (i < N_NODES) { g_deg[i] = 0; g_cursor[i] = 0; }
}

__global__ void count_deg_kernel(const int* __restrict__ dst) {
    int i = blockIdx.x * blockDim.x + threadIdx.x;
    if (i < N_EDGES) atomicAdd(&g_deg[dst[i]], 1);
}

__global__ void compute_dinv_kernel() {
    int i = blockIdx.x * blockDim.x + threadIdx.x;
    if (i < N_NODES) g_dinv[i] = rsqrtf((float)(g_deg[i] + 1));
}

// Single-block exclusive scan of g_deg -> g_rowptr (warp-shuffle based)
__global__ void __launch_bounds__(1024) scan_kernel() {
    __shared__ int wsum[32];
    __shared__ int carry_s;
    int tid = threadIdx.x, lane = tid & 31, wid = tid >> 5;
    if (tid == 0) carry_s = 0;
    __syncthreads();
    for (int base = 0; base < N_NODES; base += 1024) {
        int i = base + tid;
        int v = (i < N_NODES) ? g_deg[i] : 0;
        int incl = v;
#pragma unroll
        for (int off = 1; off < 32; off <<= 1) {
            int t = __shfl_up_sync(0xffffffffu, incl, off);
            if (lane >= off) incl += t;
        }
        if (lane == 31) wsum[wid] = incl;
        __syncthreads();
        if (wid == 0) {
            int w = wsum[lane];
#pragma unroll
            for (int off = 1; off < 32; off <<= 1) {
                int t = __shfl_up_sync(0xffffffffu, w, off);
                if (lane >= off) w += t;
            }
            wsum[lane] = w;
        }
        __syncthreads();
        int woff  = (wid == 0) ? 0 : wsum[wid - 1];
        int carry = carry_s;
        if (i < N_NODES) g_rowptr[i] = carry + woff + incl - v;
        int btot = wsum[31];
        __syncthreads();
        if (tid == 0) carry_s = carry + btot;
        __syncthreads();
    }
}

// Place each edge's src into csr_src bucketed by dst
__global__ void fill_csr_kernel(const int* __restrict__ src,
                                const int* __restrict__ dst) {
    int i = blockIdx.x * blockDim.x + threadIdx.x;
    if (i < N_EDGES) {
        int d = dst[i];
        int pos = g_rowptr[d] + atomicAdd(&g_cursor[d], 1);
        g_csrsrc[pos] = src[i];
    }
}

// ---------------------------------------------------------------- SGEMM
// C[M,128] = A[M,K] @ B[K,128], row-major, fp32.
__global__ void __launch_bounds__(256) sgemm_n128(
    const float* __restrict__ A, const float* __restrict__ B,
    float* __restrict__ C, int M, int K)
{
    const int N = 128;
    __shared__ float As[8][128];
    __shared__ float Bs[8][128];

    int tid = threadIdx.x;
    int bm  = blockIdx.x * 128;

    int tr = (tid >> 4) << 3;
    int tc = (tid & 15) << 3;

    int arow = tid >> 1;
    int acol = (tid & 1) << 2;
    int brow = tid >> 5;
    int bcol = (tid & 31) << 2;

    bool avalid = (bm + arow) < M;

    float acc[8][8];
#pragma unroll
    for (int i = 0; i < 8; i++)
#pragma unroll
        for (int j = 0; j < 8; j++) acc[i][j] = 0.0f;

    for (int k0 = 0; k0 < K; k0 += 8) {
        float4 av = make_float4(0.f, 0.f, 0.f, 0.f);
        if (avalid)
            av = *(const float4*)(A + (size_t)(bm + arow) * K + k0 + acol);
        As[acol + 0][arow] = av.x;
        As[acol + 1][arow] = av.y;
        As[acol + 2][arow] = av.z;
        As[acol + 3][arow] = av.w;

        *(float4*)&Bs[brow][bcol] =
            *(const float4*)(B + (size_t)(k0 + brow) * N + bcol);

        __syncthreads();

#pragma unroll
        for (int kk = 0; kk < 8; kk++) {
            float4 a0 = *(float4*)&As[kk][tr];
            float4 a1 = *(float4*)&As[kk][tr + 4];
            float4 b0 = *(float4*)&Bs[kk][tc];
            float4 b1 = *(float4*)&Bs[kk][tc + 4];
            float ar[8] = {a0.x, a0.y, a0.z, a0.w, a1.x, a1.y, a1.z, a1.w};
            float br[8] = {b0.x, b0.y, b0.z, b0.w, b1.x, b1.y, b1.z, b1.w};
#pragma unroll
            for (int i = 0; i < 8; i++)
#pragma unroll
                for (int j = 0; j < 8; j++)
                    acc[i][j] += ar[i] * br[j];
        }
        __syncthreads();
    }

#pragma unroll
    for (int i = 0; i < 8; i++) {
        int r = bm + tr + i;
        if (r < M) {
            *(float4*)(C + (size_t)r * N + tc) =
                make_float4(acc[i][0], acc[i][1], acc[i][2], acc[i][3]);
            *(float4*)(C + (size_t)r * N + tc + 4) =
                make_float4(acc[i][4], acc[i][5], acc[i][6], acc[i][7]);
        }
    }
}

// ---------------------------------------------------------------- gather
// One warp per dst node: acc = h[d]*dinv[d]^2 + sum_in h[s]*dinv[s]*dinv[d]
// Optional fused bias+relu epilogue (layer 1) / bias only (not used) / plain.
template<bool RELU>
__global__ void gather_kernel(const float4* __restrict__ h,
                              float4* __restrict__ out,
                              const float* __restrict__ bias)
{
    int node = (blockIdx.x * blockDim.x + threadIdx.x) >> 5;
    if (node >= N_NODES) return;
    int lane = threadIdx.x & 31;

    float dd = g_dinv[node];
    float4 v0 = __ldg(h + (size_t)node * 32 + lane);
    float w0 = dd * dd;
    float4 acc = make_float4(v0.x * w0, v0.y * w0, v0.z * w0, v0.w * w0);

    int start = g_rowptr[node];
    int cnt   = g_deg[node];

    for (int base = 0; base < cnt; base += 32) {
        int n = cnt - base; if (n > 32) n = 32;
        int s = 0; float nm = 0.f;
        if (lane < n) {
            s  = __ldg(g_csrsrc + start + base + lane);
            nm = g_dinv[s] * dd;
        }
#pragma unroll 4
        for (int j = 0; j < n; j++) {
            int   sj = __shfl_sync(0xffffffffu, s,  j);
            float nj = __shfl_sync(0xffffffffu, nm, j);
            float4 v = __ldg(h + (size_t)sj * 32 + lane);
            acc.x += v.x * nj; acc.y += v.y * nj;
            acc.z += v.z * nj; acc.w += v.w * nj;
        }
    }

    if (bias) {
        int c = lane << 2;
        acc.x += __ldg(bias + c + 0);
        acc.y += __ldg(bias + c + 1);
        acc.z += __ldg(bias + c + 2);
        acc.w += __ldg(bias + c + 3);
        if (RELU) {
            acc.x = fmaxf(acc.x, 0.f); acc.y = fmaxf(acc.y, 0.f);
            acc.z = fmaxf(acc.z, 0.f); acc.w = fmaxf(acc.w, 0.f);
        }
    }
    out[(size_t)node * 32 + lane] = acc;
}

// ---------------------------------------------------------------- epilogue
__global__ void finalize_kernel(const float4* __restrict__ agg,
                                const float* __restrict__ b2,
                                const float* __restrict__ Wh1,
                                const float* __restrict__ bh1,
                                const float* __restrict__ Wh2,
                                const float* __restrict__ bh2,
                                float* __restrict__ out1,
                                float* __restrict__ out2,
                                float4* __restrict__ outh)
{
    int w = (blockIdx.x * blockDim.x + threadIdx.x) >> 5;
    if (w >= N_NODES) return;
    int lane = threadIdx.x & 31;
    int c = lane << 2;

    float4 v = agg[(size_t)w * 32 + lane];
    v.x += __ldg(b2 + c + 0);
    v.y += __ldg(b2 + c + 1);
    v.z += __ldg(b2 + c + 2);
    v.w += __ldg(b2 + c + 3);
    outh[(size_t)w * 32 + lane] = v;

    float p[7];
#pragma unroll
    for (int j = 0; j < 4; j++) {
        p[j] = v.x * __ldg(Wh1 + (c + 0) * 4 + j)
             + v.y * __ldg(Wh1 + (c + 1) * 4 + j)
             + v.z * __ldg(Wh1 + (c + 2) * 4 + j)
             + v.w * __ldg(Wh1 + (c + 3) * 4 + j);
    }
#pragma unroll
    for (int j = 0; j < 3; j++) {
        p[4 + j] = v.x * __ldg(Wh2 + (c + 0) * 3 + j)
                 + v.y * __ldg(Wh2 + (c + 1) * 3 + j)
                 + v.z * __ldg(Wh2 + (c + 2) * 3 + j)
                 + v.w * __ldg(Wh2 + (c + 3) * 3 + j);
    }
#pragma unroll
    for (int j = 0; j < 7; j++) {
#pragma unroll
        for (int off = 16; off > 0; off >>= 1)
            p[j] += __shfl_xor_sync(0xffffffffu, p[j], off);
    }
    if (lane == 0) {
#pragma unroll
        for (int j = 0; j < 4; j++) out1[(size_t)w * 4 + j] = p[j] + __ldg(bh1 + j);
#pragma unroll
        for (int j = 0; j < 3; j++) out2[(size_t)w * 3 + j] = p[4 + j] + __ldg(bh2 + j);
    }
}

// ---------------------------------------------------------------- launch
extern "C" void kernel_launch(void* const* d_in, const int* in_sizes, int n_in,
                              void* d_out, int out_size)
{
    const float* x   = (const float*)d_in[0];
    const int*   ei  = (const int*)d_in[1];        // [2, E]
    const float* W1  = (const float*)d_in[2];
    const float* b1  = (const float*)d_in[3];
    const float* W2  = (const float*)d_in[4];
    const float* b2  = (const float*)d_in[5];
    const float* Wh1 = (const float*)d_in[6];
    const float* bh1 = (const float*)d_in[7];
    const float* Wh2 = (const float*)d_in[8];
    const float* bh2 = (const float*)d_in[9];

    const int* src = ei;
    const int* dst = ei + N_EDGES;

    float* out  = (float*)d_out;
    float* out1 = out;                                    // [N, 4]
    float* out2 = out + (size_t)N_NODES * 4;              // [N, 3]
    float4* outh = (float4*)(out + (size_t)N_NODES * 7);  // [N, 128]

    float* B0;  cudaGetSymbolAddress((void**)&B0, g_buf0);
    float* B1;  cudaGetSymbolAddress((void**)&B1, g_buf1);

    const int T = 256;
    int gNodes = (N_NODES + T - 1) / T;
    int gEdges = (N_EDGES + T - 1) / T;
    int gWarpN = (N_NODES * 32 + T - 1) / T;
    int gGemm  = (N_NODES + 127) / 128;

    // CSR-by-dst build + normalization
    zero_kernel<<<gNodes, T>>>();
    count_deg_kernel<<<gEdges, T>>>(dst);
    compute_dinv_kernel<<<gNodes, T>>>();
    scan_kernel<<<1, 1024>>>();
    fill_csr_kernel<<<gEdges, T>>>(src, dst);

    // Layer 1: h1 = x @ W1 -> B0 ; agg+bias+relu -> B1
    sgemm_n128<<<gGemm, T>>>(x, W1, B0, N_NODES, F_IN);
    gather_kernel<true><<<gWarpN, T>>>((const float4*)B0, (float4*)B1, b1);

    // Layer 2: h2 = h1r @ W2 -> B0 ; agg -> B1
    sgemm_n128<<<gGemm, T>>>(B1, W2, B0, N_NODES, HDIM);
    gather_kernel<false><<<gWarpN, T>>>((const float4*)B0, (float4*)B1, nullptr);

    // Epilogue: h = agg2 + b2, heads
    finalize_kernel<<<gWarpN, T>>>((const float4*)B1, b2, Wh1, bh1, Wh2, bh2,
                                   out1, out2, outh);

    (void)in_sizes; (void)n_in; (void)out_size;
}

// round 5
// speedup vs baseline: 2.3380x; 1.1918x over previous
#include <cuda_runtime.h>

#define N_NODES 50000
#define N_EDGES 800000
#define F_IN    256
#define HDIM    128
#define NB_SCAN ((N_NODES + 255) / 256)   // 196

// Scratch (device globals)
__device__ float g_buf0[N_NODES * HDIM];
__device__ float g_buf1[N_NODES * HDIM];
__device__ int   g_deg[N_NODES];
__device__ int   g_rowptr[N_NODES];
__device__ int   g_cursor[N_NODES];
__device__ int   g_csrsrc[N_EDGES];
__device__ float g_dinv[N_NODES];
__device__ int   g_bsum[256];

// ---------------------------------------------------------------- degree
__global__ void zero_kernel() {
    int i = blockIdx.x * blockDim.x + threadIdx.x;
    if (i < N_NODES) { g_deg[i] = 0; g_cursor[i] = 0; }
}

__global__ void count_deg_kernel(const int* __restrict__ dst) {
    int i = blockIdx.x * blockDim.x + threadIdx.x;
    if (i < N_EDGES) atomicAdd(&g_deg[dst[i]], 1);
}

__global__ void compute_dinv_kernel() {
    int i = blockIdx.x * blockDim.x + threadIdx.x;
    if (i < N_NODES) g_dinv[i] = rsqrtf((float)(g_deg[i] + 1));
}

// ------------------------------------------------- 3-phase exclusive scan
// Phase 1: per-block (256 elems) exclusive scan into g_rowptr, block sums out.
__global__ void __launch_bounds__(256) scan_local_kernel() {
    __shared__ int wsum[8];
    int tid = threadIdx.x, lane = tid & 31, wid = tid >> 5;
    int i = blockIdx.x * 256 + tid;
    int v = (i < N_NODES) ? g_deg[i] : 0;
    int incl = v;
#pragma unroll
    for (int off = 1; off < 32; off <<= 1) {
        int t = __shfl_up_sync(0xffffffffu, incl, off);
        if (lane >= off) incl += t;
    }
    if (lane == 31) wsum[wid] = incl;
    __syncthreads();
    if (wid == 0 && lane < 8) {
        int w = wsum[lane];
#pragma unroll
        for (int off = 1; off < 8; off <<= 1) {
            int t = __shfl_up_sync(0xffu, w, off);
            if (lane >= off) w += t;
        }
        wsum[lane] = w;
    }
    __syncthreads();
    int excl = incl - v + (wid ? wsum[wid - 1] : 0);
    if (i < N_NODES) g_rowptr[i] = excl;
    if (tid == 255) g_bsum[blockIdx.x] = wsum[7];
}

// Phase 2: single block scans the 196 block sums (exclusive, in place).
__global__ void __launch_bounds__(256) scan_block_kernel() {
    __shared__ int wsum[8];
    int tid = threadIdx.x, lane = tid & 31, wid = tid >> 5;
    int v = (tid < NB_SCAN) ? g_bsum[tid] : 0;
    int incl = v;
#pragma unroll
    for (int off = 1; off < 32; off <<= 1) {
        int t = __shfl_up_sync(0xffffffffu, incl, off);
        if (lane >= off) incl += t;
    }
    if (lane == 31) wsum[wid] = incl;
    __syncthreads();
    if (wid == 0 && lane < 8) {
        int w = wsum[lane];
#pragma unroll
        for (int off = 1; off < 8; off <<= 1) {
            int t = __shfl_up_sync(0xffu, w, off);
            if (lane >= off) w += t;
        }
        wsum[lane] = w;
    }
    __syncthreads();
    int excl = incl - v + (wid ? wsum[wid - 1] : 0);
    if (tid < NB_SCAN) g_bsum[tid] = excl;
}

// Phase 3: add block offsets.
__global__ void scan_add_kernel() {
    int i = blockIdx.x * blockDim.x + threadIdx.x;
    if (i < N_NODES) g_rowptr[i] += g_bsum[i >> 8];
}

// Place each edge's src into csr_src bucketed by dst
__global__ void fill_csr_kernel(const int* __restrict__ src,
                                const int* __restrict__ dst) {
    int i = blockIdx.x * blockDim.x + threadIdx.x;
    if (i < N_EDGES) {
        int d = dst[i];
        int pos = g_rowptr[d] + atomicAdd(&g_cursor[d], 1);
        g_csrsrc[pos] = src[i];
    }
}

// ---------------------------------------------------------------- SGEMM
// C[M,128] = A[M,K] @ B[K,128]. BM=BN=128, BK=16, double-buffered smem,
// 256 threads, 8x8 register tile. K % 16 == 0.
__global__ void __launch_bounds__(256) sgemm_n128(
    const float* __restrict__ A, const float* __restrict__ B,
    float* __restrict__ C, int M, int K)
{
    const int N = 128;
    __shared__ float As[2][16][128];
    __shared__ float Bs[2][16][128];

    int tid = threadIdx.x;
    int bm  = blockIdx.x * 128;

    int tr = (tid >> 4) << 3;
    int tc = (tid & 15) << 3;

    // A: 128 rows x 16 cols per tile -> 2 float4 per thread
    int ar = tid >> 2;            // 0..63 (rows ar, ar+64)
    int ac = (tid & 3) << 2;      // 0,4,8,12
    // B: 16 rows x 128 cols per tile -> 2 float4 per thread
    int br = tid >> 5;            // 0..7 (rows br, br+8)
    int bc = (tid & 31) << 2;

    bool av0 = (bm + ar)      < M;
    bool av1 = (bm + ar + 64) < M;

    float acc[8][8];
#pragma unroll
    for (int i = 0; i < 8; i++)
#pragma unroll
        for (int j = 0; j < 8; j++) acc[i][j] = 0.0f;

    const int nt = K >> 4;

    // Prologue: tile 0 -> buffer 0
    {
        float4 a0 = make_float4(0.f,0.f,0.f,0.f), a1 = a0;
        if (av0) a0 = *(const float4*)(A + (size_t)(bm + ar)      * K + ac);
        if (av1) a1 = *(const float4*)(A + (size_t)(bm + ar + 64) * K + ac);
        As[0][ac+0][ar] = a0.x; As[0][ac+1][ar] = a0.y;
        As[0][ac+2][ar] = a0.z; As[0][ac+3][ar] = a0.w;
        As[0][ac+0][ar+64] = a1.x; As[0][ac+1][ar+64] = a1.y;
        As[0][ac+2][ar+64] = a1.z; As[0][ac+3][ar+64] = a1.w;
        *(float4*)&Bs[0][br  ][bc] = *(const float4*)(B + (size_t)(br    ) * N + bc);
        *(float4*)&Bs[0][br+8][bc] = *(const float4*)(B + (size_t)(br + 8) * N + bc);
    }
    __syncthreads();

    for (int t = 0; t < nt; t++) {
        int cur = t & 1;
        float4 a0, a1, b0, b1;
        if (t + 1 < nt) {
            int k0 = (t + 1) << 4;
            a0 = make_float4(0.f,0.f,0.f,0.f); a1 = a0;
            if (av0) a0 = *(const float4*)(A + (size_t)(bm + ar)      * K + k0 + ac);
            if (av1) a1 = *(const float4*)(A + (size_t)(bm + ar + 64) * K + k0 + ac);
            b0 = *(const float4*)(B + (size_t)(k0 + br    ) * N + bc);
            b1 = *(const float4*)(B + (size_t)(k0 + br + 8) * N + bc);
        }

#pragma unroll
        for (int kk = 0; kk < 16; kk++) {
            float4 x0 = *(float4*)&As[cur][kk][tr];
            float4 x1 = *(float4*)&As[cur][kk][tr + 4];
            float4 y0 = *(float4*)&Bs[cur][kk][tc];
            float4 y1 = *(float4*)&Bs[cur][kk][tc + 4];
            float xr[8] = {x0.x,x0.y,x0.z,x0.w,x1.x,x1.y,x1.z,x1.w};
            float yr[8] = {y0.x,y0.y,y0.z,y0.w,y1.x,y1.y,y1.z,y1.w};
#pragma unroll
            for (int i = 0; i < 8; i++)
#pragma unroll
                for (int j = 0; j < 8; j++)
                    acc[i][j] += xr[i] * yr[j];
        }

        if (t + 1 < nt) {
            int nxt = cur ^ 1;
            As[nxt][ac+0][ar] = a0.x; As[nxt][ac+1][ar] = a0.y;
            As[nxt][ac+2][ar] = a0.z; As[nxt][ac+3][ar] = a0.w;
            As[nxt][ac+0][ar+64] = a1.x; As[nxt][ac+1][ar+64] = a1.y;
            As[nxt][ac+2][ar+64] = a1.z; As[nxt][ac+3][ar+64] = a1.w;
            *(float4*)&Bs[nxt][br  ][bc] = b0;
            *(float4*)&Bs[nxt][br+8][bc] = b1;
            __syncthreads();
        }
    }

#pragma unroll
    for (int i = 0; i < 8; i++) {
        int r = bm + tr + i;
        if (r < M) {
            *(float4*)(C + (size_t)r * N + tc) =
                make_float4(acc[i][0], acc[i][1], acc[i][2], acc[i][3]);
            *(float4*)(C + (size_t)r * N + tc + 4) =
                make_float4(acc[i][4], acc[i][5], acc[i][6], acc[i][7]);
        }
    }
}

// ---------------------------------------------------------------- gather L1
// One warp per dst node: acc = h[d]*dinv[d]^2 + sum_in h[s]*dinv[s]*dinv[d],
// then +bias, relu.
__global__ void gather_relu_kernel(const float4* __restrict__ h,
                                   float4* __restrict__ out,
                                   const float* __restrict__ bias)
{
    int node = (blockIdx.x * blockDim.x + threadIdx.x) >> 5;
    if (node >= N_NODES) return;
    int lane = threadIdx.x & 31;

    float dd = g_dinv[node];
    float4 v0 = __ldg(h + (size_t)node * 32 + lane);
    float w0 = dd * dd;
    float4 acc = make_float4(v0.x * w0, v0.y * w0, v0.z * w0, v0.w * w0);

    int start = g_rowptr[node];
    int cnt   = g_deg[node];

    for (int base = 0; base < cnt; base += 32) {
        int n = cnt - base; if (n > 32) n = 32;
        int s = 0; float nm = 0.f;
        if (lane < n) {
            s  = __ldg(g_csrsrc + start + base + lane);
            nm = g_dinv[s] * dd;
        }
#pragma unroll 4
        for (int j = 0; j < n; j++) {
            int   sj = __shfl_sync(0xffffffffu, s,  j);
            float nj = __shfl_sync(0xffffffffu, nm, j);
            float4 v = __ldg(h + (size_t)sj * 32 + lane);
            acc.x += v.x * nj; acc.y += v.y * nj;
            acc.z += v.z * nj; acc.w += v.w * nj;
        }
    }

    int c = lane << 2;
    acc.x = fmaxf(acc.x + __ldg(bias + c + 0), 0.f);
    acc.y = fmaxf(acc.y + __ldg(bias + c + 1), 0.f);
    acc.z = fmaxf(acc.z + __ldg(bias + c + 2), 0.f);
    acc.w = fmaxf(acc.w + __ldg(bias + c + 3), 0.f);
    out[(size_t)node * 32 + lane] = acc;
}

// ------------------------------------------- gather L2 + finalize (fused)
// acc = gather(h2) ; h = acc + b2 -> outh ; out1 = h@Wh1+bh1 ; out2 = h@Wh2+bh2
__global__ void gather_final_kernel(const float4* __restrict__ h,
                                    const float* __restrict__ b2,
                                    const float* __restrict__ Wh1,
                                    const float* __restrict__ bh1,
                                    const float* __restrict__ Wh2,
                                    const float* __restrict__ bh2,
                                    float* __restrict__ out1,
                                    float* __restrict__ out2,
                                    float4* __restrict__ outh)
{
    int node = (blockIdx.x * blockDim.x + threadIdx.x) >> 5;
    if (node >= N_NODES) return;
    int lane = threadIdx.x & 31;

    float dd = g_dinv[node];
    float4 v0 = __ldg(h + (size_t)node * 32 + lane);
    float w0 = dd * dd;
    float4 acc = make_float4(v0.x * w0, v0.y * w0, v0.z * w0, v0.w * w0);

    int start = g_rowptr[node];
    int cnt   = g_deg[node];

    for (int base = 0; base < cnt; base += 32) {
        int n = cnt - base; if (n > 32) n = 32;
        int s = 0; float nm = 0.f;
        if (lane < n) {
            s  = __ldg(g_csrsrc + start + base + lane);
            nm = g_dinv[s] * dd;
        }
#pragma unroll 4
        for (int j = 0; j < n; j++) {
            int   sj = __shfl_sync(0xffffffffu, s,  j);
            float nj = __shfl_sync(0xffffffffu, nm, j);
            float4 v = __ldg(h + (size_t)sj * 32 + lane);
            acc.x += v.x * nj; acc.y += v.y * nj;
            acc.z += v.z * nj; acc.w += v.w * nj;
        }
    }

    int c = lane << 2;
    acc.x += __ldg(b2 + c + 0);
    acc.y += __ldg(b2 + c + 1);
    acc.z += __ldg(b2 + c + 2);
    acc.w += __ldg(b2 + c + 3);
    outh[(size_t)node * 32 + lane] = acc;

    float p[7];
#pragma unroll
    for (int j = 0; j < 4; j++) {
        p[j] = acc.x * __ldg(Wh1 + (c + 0) * 4 + j)
             + acc.y * __ldg(Wh1 + (c + 1) * 4 + j)
             + acc.z * __ldg(Wh1 + (c + 2) * 4 + j)
             + acc.w * __ldg(Wh1 + (c + 3) * 4 + j);
    }
#pragma unroll
    for (int j = 0; j < 3; j++) {
        p[4 + j] = acc.x * __ldg(Wh2 + (c + 0) * 3 + j)
                 + acc.y * __ldg(Wh2 + (c + 1) * 3 + j)
                 + acc.z * __ldg(Wh2 + (c + 2) * 3 + j)
                 + acc.w * __ldg(Wh2 + (c + 3) * 3 + j);
    }
#pragma unroll
    for (int j = 0; j < 7; j++) {
#pragma unroll
        for (int off = 16; off > 0; off >>= 1)
            p[j] += __shfl_xor_sync(0xffffffffu, p[j], off);
    }
    if (lane == 0) {
#pragma unroll
        for (int j = 0; j < 4; j++) out1[(size_t)node * 4 + j] = p[j] + __ldg(bh1 + j);
#pragma unroll
        for (int j = 0; j < 3; j++) out2[(size_t)node * 3 + j] = p[4 + j] + __ldg(bh2 + j);
    }
}

// ---------------------------------------------------------------- launch
extern "C" void kernel_launch(void* const* d_in, const int* in_sizes, int n_in,
                              void* d_out, int out_size)
{
    const float* x   = (const float*)d_in[0];
    const int*   ei  = (const int*)d_in[1];        // [2, E]
    const float* W1  = (const float*)d_in[2];
    const float* b1  = (const float*)d_in[3];
    const float* W2  = (const float*)d_in[4];
    const float* b2  = (const float*)d_in[5];
    const float* Wh1 = (const float*)d_in[6];
    const float* bh1 = (const float*)d_in[7];
    const float* Wh2 = (const float*)d_in[8];
    const float* bh2 = (const float*)d_in[9];

    const int* src = ei;
    const int* dst = ei + N_EDGES;

    float* out  = (float*)d_out;
    float* out1 = out;                                    // [N, 4]
    float* out2 = out + (size_t)N_NODES * 4;              // [N, 3]
    float4* outh = (float4*)(out + (size_t)N_NODES * 7);  // [N, 128]

    float* B0;  cudaGetSymbolAddress((void**)&B0, g_buf0);
    float* B1;  cudaGetSymbolAddress((void**)&B1, g_buf1);

    const int T = 256;
    int gNodes = (N_NODES + T - 1) / T;
    int gEdges = (N_EDGES + T - 1) / T;
    int gWarpN = (N_NODES * 32 + T - 1) / T;
    int gGemm  = (N_NODES + 127) / 128;

    // CSR-by-dst build + normalization
    zero_kernel<<<gNodes, T>>>();
    count_deg_kernel<<<gEdges, T>>>(dst);
    compute_dinv_kernel<<<gNodes, T>>>();
    scan_local_kernel<<<NB_SCAN, T>>>();
    scan_block_kernel<<<1, T>>>();
    scan_add_kernel<<<gNodes, T>>>();
    fill_csr_kernel<<<gEdges, T>>>(src, dst);

    // Layer 1: h1 = x @ W1 -> B0 ; agg+bias+relu -> B1
    sgemm_n128<<<gGemm, T>>>(x, W1, B0, N_NODES, F_IN);
    gather_relu_kernel<<<gWarpN, T>>>((const float4*)B0, (float4*)B1, b1);

    // Layer 2: h2 = h1r @ W2 -> B0 ; fused gather + heads
    sgemm_n128<<<gGemm, T>>>(B1, W2, B0, N_NODES, HDIM);
    gather_final_kernel<<<gWarpN, T>>>((const float4*)B0, b2, Wh1, bh1, Wh2, bh2,
                                       out1, out2, outh);

    (void)in_sizes; (void)n_in; (void)out_size;
}

// round 6
// speedup vs baseline: 2.9741x; 1.2721x over previous
#include <cuda_runtime.h>
#include <cuda_bf16.h>

#define N_NODES 50000
#define N_EDGES 800000
#define F_IN    256
#define HDIM    128
#define NB_SCAN ((N_NODES + 255) / 256)   // 196

// Scratch (device globals)
__device__ float g_buf0[N_NODES * HDIM];
__device__ float g_buf1[N_NODES * HDIM];
__device__ int   g_deg[N_NODES];
__device__ int   g_rowptr[N_NODES];
__device__ int   g_cursor[N_NODES];
__device__ int   g_csrsrc[N_EDGES];
__device__ float g_dinv[N_NODES];
__device__ int   g_bsum[256];

// ---------------------------------------------------------------- degree
__global__ void zero_kernel() {
    int i = blockIdx.x * blockDim.x + threadIdx.x;
    if (i < N_NODES) { g_deg[i] = 0; g_cursor[i] = 0; }
}

__global__ void count_deg_kernel(const int* __restrict__ dst) {
    int i = blockIdx.x * blockDim.x + threadIdx.x;
    if (i < N_EDGES) atomicAdd(&g_deg[dst[i]], 1);
}

__global__ void compute_dinv_kernel() {
    int i = blockIdx.x * blockDim.x + threadIdx.x;
    if (i < N_NODES) g_dinv[i] = rsqrtf((float)(g_deg[i] + 1));
}

// ------------------------------------------------- 3-phase exclusive scan
__global__ void __launch_bounds__(256) scan_local_kernel() {
    __shared__ int wsum[8];
    int tid = threadIdx.x, lane = tid & 31, wid = tid >> 5;
    int i = blockIdx.x * 256 + tid;
    int v = (i < N_NODES) ? g_deg[i] : 0;
    int incl = v;
#pragma unroll
    for (int off = 1; off < 32; off <<= 1) {
        int t = __shfl_up_sync(0xffffffffu, incl, off);
        if (lane >= off) incl += t;
    }
    if (lane == 31) wsum[wid] = incl;
    __syncthreads();
    if (wid == 0 && lane < 8) {
        int w = wsum[lane];
#pragma unroll
        for (int off = 1; off < 8; off <<= 1) {
            int t = __shfl_up_sync(0xffu, w, off);
            if (lane >= off) w += t;
        }
        wsum[lane] = w;
    }
    __syncthreads();
    int excl = incl - v + (wid ? wsum[wid - 1] : 0);
    if (i < N_NODES) g_rowptr[i] = excl;
    if (tid == 255) g_bsum[blockIdx.x] = wsum[7];
}

__global__ void __launch_bounds__(256) scan_block_kernel() {
    __shared__ int wsum[8];
    int tid = threadIdx.x, lane = tid & 31, wid = tid >> 5;
    int v = (tid < NB_SCAN) ? g_bsum[tid] : 0;
    int incl = v;
#pragma unroll
    for (int off = 1; off < 32; off <<= 1) {
        int t = __shfl_up_sync(0xffffffffu, incl, off);
        if (lane >= off) incl += t;
    }
    if (lane == 31) wsum[wid] = incl;
    __syncthreads();
    if (wid == 0 && lane < 8) {
        int w = wsum[lane];
#pragma unroll
        for (int off = 1; off < 8; off <<= 1) {
            int t = __shfl_up_sync(0xffu, w, off);
            if (lane >= off) w += t;
        }
        wsum[lane] = w;
    }
    __syncthreads();
    int excl = incl - v + (wid ? wsum[wid - 1] : 0);
    if (tid < NB_SCAN) g_bsum[tid] = excl;
}

__global__ void scan_add_kernel() {
    int i = blockIdx.x * blockDim.x + threadIdx.x;
    if (i < N_NODES) g_rowptr[i] += g_bsum[i >> 8];
}

__global__ void fill_csr_kernel(const int* __restrict__ src,
                                const int* __restrict__ dst) {
    int i = blockIdx.x * blockDim.x + threadIdx.x;
    if (i < N_EDGES) {
        int d = dst[i];
        int pos = g_rowptr[d] + atomicAdd(&g_cursor[d], 1);
        g_csrsrc[pos] = src[i];
    }
}

// ---------------------------------------------------------------- MMA GEMM
// C[M,128] = A[M,K] @ B[K,128] fp32, computed via bf16 2-split (3 MMAs):
// A = Ah + Al, B = Bh + Bl ;  C ≈ Ah*Bh + Ah*Bl + Al*Bh  (error ~2^-16)
// CTA: 128x128 tile, BK=16, double-buffered smem, 256 threads (8 warps),
// warp tile 32x64, mma.sync.m16n8k16 bf16 with fp32 accum.

__device__ __forceinline__ void ldsm4(unsigned& r0, unsigned& r1,
                                      unsigned& r2, unsigned& r3,
                                      const void* p) {
    unsigned a = (unsigned)__cvta_generic_to_shared(p);
    asm volatile("ldmatrix.sync.aligned.m8n8.x4.shared.b16 {%0,%1,%2,%3}, [%4];"
                 : "=r"(r0), "=r"(r1), "=r"(r2), "=r"(r3) : "r"(a));
}

__device__ __forceinline__ void ldsm4t(unsigned& r0, unsigned& r1,
                                       unsigned& r2, unsigned& r3,
                                       const void* p) {
    unsigned a = (unsigned)__cvta_generic_to_shared(p);
    asm volatile("ldmatrix.sync.aligned.m8n8.x4.trans.shared.b16 {%0,%1,%2,%3}, [%4];"
                 : "=r"(r0), "=r"(r1), "=r"(r2), "=r"(r3) : "r"(a));
}

__device__ __forceinline__ void mma16816(float* d, const unsigned* a,
                                         unsigned b0, unsigned b1) {
    asm volatile(
        "mma.sync.aligned.m16n8k16.row.col.f32.bf16.bf16.f32 "
        "{%0,%1,%2,%3}, {%4,%5,%6,%7}, {%8,%9}, {%0,%1,%2,%3};\n"
        : "+f"(d[0]), "+f"(d[1]), "+f"(d[2]), "+f"(d[3])
        : "r"(a[0]), "r"(a[1]), "r"(a[2]), "r"(a[3]), "r"(b0), "r"(b1));
}

__device__ __forceinline__ void split2(float x, float y,
                                       __nv_bfloat162& hi, __nv_bfloat162& lo) {
    __nv_bfloat16 hx = __float2bfloat16(x);
    __nv_bfloat16 hy = __float2bfloat16(y);
    __nv_bfloat16 lx = __float2bfloat16(x - __bfloat162float(hx));
    __nv_bfloat16 ly = __float2bfloat16(y - __bfloat162float(hy));
    hi = __halves2bfloat162(hx, hy);
    lo = __halves2bfloat162(lx, ly);
}

#define SA_LD 24   // 16 + 8 pad (stride 48B: conflict-free ldmatrix)
#define SB_LD 136  // 128 + 8 pad (stride 272B: conflict-free ldmatrix)

__global__ void __launch_bounds__(256) gemm_bf16x3(
    const float* __restrict__ A, const float* __restrict__ B,
    float* __restrict__ C, int M, int K)
{
    __shared__ __align__(16) __nv_bfloat16 sAh[2][128][SA_LD];
    __shared__ __align__(16) __nv_bfloat16 sAl[2][128][SA_LD];
    __shared__ __align__(16) __nv_bfloat16 sBh[2][16][SB_LD];
    __shared__ __align__(16) __nv_bfloat16 sBl[2][16][SB_LD];

    const int tid  = threadIdx.x;
    const int lane = tid & 31;
    const int wid  = tid >> 5;
    const int bm   = blockIdx.x * 128;

    const int wm = (wid >> 1) * 32;   // warp M offset (0,32,64,96)
    const int wn = (wid & 1) * 64;    // warp N offset (0,64)

    // staging thread mapping
    const int arow = tid >> 1;             // 0..127
    const int acg  = (tid & 1) * 8;        // 0 or 8
    const int brow = tid >> 4;             // 0..15
    const int bcg  = (tid & 15) * 8;       // 0..120

    const bool avalid = (bm + arow) < M;

    // ldmatrix addresses (within-tile)
    const int a_r = ((lane >> 3) & 1) * 8 + (lane & 7);  // row in 16-tile
    const int a_c = (lane >> 4) * 8;                     // 0 or 8
    const int b_k = ((lane >> 3) & 1) * 8 + (lane & 7);  // k row
    const int b_n = (lane >> 4) * 8;                     // 0 or 8

    float acc[2][8][4];
#pragma unroll
    for (int i = 0; i < 2; i++)
#pragma unroll
        for (int j = 0; j < 8; j++)
#pragma unroll
            for (int q = 0; q < 4; q++) acc[i][j][q] = 0.0f;

    const int nt = K >> 4;

    // ---- stage + convert chunk 0 into buffer 0
    {
        float4 a0 = make_float4(0.f,0.f,0.f,0.f), a1 = a0;
        if (avalid) {
            a0 = *(const float4*)(A + (size_t)(bm + arow) * K + acg);
            a1 = *(const float4*)(A + (size_t)(bm + arow) * K + acg + 4);
        }
        float4 b0 = *(const float4*)(B + (size_t)brow * 128 + bcg);
        float4 b1 = *(const float4*)(B + (size_t)brow * 128 + bcg + 4);
        __nv_bfloat162 h, l;
        split2(a0.x, a0.y, h, l);
        *(__nv_bfloat162*)&sAh[0][arow][acg+0] = h; *(__nv_bfloat162*)&sAl[0][arow][acg+0] = l;
        split2(a0.z, a0.w, h, l);
        *(__nv_bfloat162*)&sAh[0][arow][acg+2] = h; *(__nv_bfloat162*)&sAl[0][arow][acg+2] = l;
        split2(a1.x, a1.y, h, l);
        *(__nv_bfloat162*)&sAh[0][arow][acg+4] = h; *(__nv_bfloat162*)&sAl[0][arow][acg+4] = l;
        split2(a1.z, a1.w, h, l);
        *(__nv_bfloat162*)&sAh[0][arow][acg+6] = h; *(__nv_bfloat162*)&sAl[0][arow][acg+6] = l;
        split2(b0.x, b0.y, h, l);
        *(__nv_bfloat162*)&sBh[0][brow][bcg+0] = h; *(__nv_bfloat162*)&sBl[0][brow][bcg+0] = l;
        split2(b0.z, b0.w, h, l);
        *(__nv_bfloat162*)&sBh[0][brow][bcg+2] = h; *(__nv_bfloat162*)&sBl[0][brow][bcg+2] = l;
        split2(b1.x, b1.y, h, l);
        *(__nv_bfloat162*)&sBh[0][brow][bcg+4] = h; *(__nv_bfloat162*)&sBl[0][brow][bcg+4] = l;
        split2(b1.z, b1.w, h, l);
        *(__nv_bfloat162*)&sBh[0][brow][bcg+6] = h; *(__nv_bfloat162*)&sBl[0][brow][bcg+6] = l;
    }
    __syncthreads();

    for (int t = 0; t < nt; t++) {
        const int cur = t & 1;

        // stage next chunk from gmem
        float4 a0, a1, b0, b1;
        const bool more = (t + 1) < nt;
        if (more) {
            int k0 = (t + 1) << 4;
            a0 = make_float4(0.f,0.f,0.f,0.f); a1 = a0;
            if (avalid) {
                a0 = *(const float4*)(A + (size_t)(bm + arow) * K + k0 + acg);
                a1 = *(const float4*)(A + (size_t)(bm + arow) * K + k0 + acg + 4);
            }
            b0 = *(const float4*)(B + (size_t)(k0 + brow) * 128 + bcg);
            b1 = *(const float4*)(B + (size_t)(k0 + brow) * 128 + bcg + 4);
        }

        // ---- MMA over current buffer
        unsigned ah[2][4], al[2][4];
#pragma unroll
        for (int tm = 0; tm < 2; tm++) {
            ldsm4(ah[tm][0], ah[tm][1], ah[tm][2], ah[tm][3],
                  &sAh[cur][wm + tm*16 + a_r][a_c]);
            ldsm4(al[tm][0], al[tm][1], al[tm][2], al[tm][3],
                  &sAl[cur][wm + tm*16 + a_r][a_c]);
        }
#pragma unroll
        for (int np = 0; np < 4; np++) {
            unsigned bh[4], bl[4];
            int n0 = wn + np * 16;
            ldsm4t(bh[0], bh[1], bh[2], bh[3], &sBh[cur][b_k][n0 + b_n]);
            ldsm4t(bl[0], bl[1], bl[2], bl[3], &sBl[cur][b_k][n0 + b_n]);
#pragma unroll
            for (int tm = 0; tm < 2; tm++) {
#pragma unroll
                for (int h = 0; h < 2; h++) {
                    float* d = acc[tm][np * 2 + h];
                    mma16816(d, ah[tm], bh[2*h], bh[2*h + 1]);
                    mma16816(d, ah[tm], bl[2*h], bl[2*h + 1]);
                    mma16816(d, al[tm], bh[2*h], bh[2*h + 1]);
                }
            }
        }

        // ---- convert + store next chunk
        if (more) {
            const int nxt = cur ^ 1;
            __nv_bfloat162 h, l;
            split2(a0.x, a0.y, h, l);
            *(__nv_bfloat162*)&sAh[nxt][arow][acg+0] = h; *(__nv_bfloat162*)&sAl[nxt][arow][acg+0] = l;
            split2(a0.z, a0.w, h, l);
            *(__nv_bfloat162*)&sAh[nxt][arow][acg+2] = h; *(__nv_bfloat162*)&sAl[nxt][arow][acg+2] = l;
            split2(a1.x, a1.y, h, l);
            *(__nv_bfloat162*)&sAh[nxt][arow][acg+4] = h; *(__nv_bfloat162*)&sAl[nxt][arow][acg+4] = l;
            split2(a1.z, a1.w, h, l);
            *(__nv_bfloat162*)&sAh[nxt][arow][acg+6] = h; *(__nv_bfloat162*)&sAl[nxt][arow][acg+6] = l;
            split2(b0.x, b0.y, h, l);
            *(__nv_bfloat162*)&sBh[nxt][brow][bcg+0] = h; *(__nv_bfloat162*)&sBl[nxt][brow][bcg+0] = l;
            split2(b0.z, b0.w, h, l);
            *(__nv_bfloat162*)&sBh[nxt][brow][bcg+2] = h; *(__nv_bfloat162*)&sBl[nxt][brow][bcg+2] = l;
            split2(b1.x, b1.y, h, l);
            *(__nv_bfloat162*)&sBh[nxt][brow][bcg+4] = h; *(__nv_bfloat162*)&sBl[nxt][brow][bcg+4] = l;
            split2(b1.z, b1.w, h, l);
            *(__nv_bfloat162*)&sBh[nxt][brow][bcg+6] = h; *(__nv_bfloat162*)&sBl[nxt][brow][bcg+6] = l;
        }
        __syncthreads();
    }

    // ---- epilogue: write accumulators
    const int g = lane >> 2;       // 0..7
    const int tq = lane & 3;       // 0..3
#pragma unroll
    for (int tm = 0; tm < 2; tm++) {
        int r0 = bm + wm + tm * 16 + g;
        int r1 = r0 + 8;
#pragma unroll
        for (int n8 = 0; n8 < 8; n8++) {
            int col = wn + n8 * 8 + tq * 2;
            float* d = acc[tm][n8];
            if (r0 < M) *(float2*)(C + (size_t)r0 * 128 + col) = make_float2(d[0], d[1]);
            if (r1 < M) *(float2*)(C + (size_t)r1 * 128 + col) = make_float2(d[2], d[3]);
        }
    }
}

// ---------------------------------------------------------------- gather L1
__global__ void gather_relu_kernel(const float4* __restrict__ h,
                                   float4* __restrict__ out,
                                   const float* __restrict__ bias)
{
    int node = (blockIdx.x * blockDim.x + threadIdx.x) >> 5;
    if (node >= N_NODES) return;
    int lane = threadIdx.x & 31;

    float dd = g_dinv[node];
    float4 v0 = __ldg(h + (size_t)node * 32 + lane);
    float w0 = dd * dd;
    float4 acc = make_float4(v0.x * w0, v0.y * w0, v0.z * w0, v0.w * w0);

    int start = g_rowptr[node];
    int cnt   = g_deg[node];

    for (int base = 0; base < cnt; base += 32) {
        int n = cnt - base; if (n > 32) n = 32;
        int s = 0; float nm = 0.f;
        if (lane < n) {
            s  = __ldg(g_csrsrc + start + base + lane);
            nm = g_dinv[s] * dd;
        }
#pragma unroll 4
        for (int j = 0; j < n; j++) {
            int   sj = __shfl_sync(0xffffffffu, s,  j);
            float nj = __shfl_sync(0xffffffffu, nm, j);
            float4 v = __ldg(h + (size_t)sj * 32 + lane);
            acc.x += v.x * nj; acc.y += v.y * nj;
            acc.z += v.z * nj; acc.w += v.w * nj;
        }
    }

    int c = lane << 2;
    acc.x = fmaxf(acc.x + __ldg(bias + c + 0), 0.f);
    acc.y = fmaxf(acc.y + __ldg(bias + c + 1), 0.f);
    acc.z = fmaxf(acc.z + __ldg(bias + c + 2), 0.f);
    acc.w = fmaxf(acc.w + __ldg(bias + c + 3), 0.f);
    out[(size_t)node * 32 + lane] = acc;
}

// ------------------------------------------- gather L2 + finalize (fused)
__global__ void gather_final_kernel(const float4* __restrict__ h,
                                    const float* __restrict__ b2,
                                    const float* __restrict__ Wh1,
                                    const float* __restrict__ bh1,
                                    const float* __restrict__ Wh2,
                                    const float* __restrict__ bh2,
                                    float* __restrict__ out1,
                                    float* __restrict__ out2,
                                    float4* __restrict__ outh)
{
    int node = (blockIdx.x * blockDim.x + threadIdx.x) >> 5;
    if (node >= N_NODES) return;
    int lane = threadIdx.x & 31;

    float dd = g_dinv[node];
    float4 v0 = __ldg(h + (size_t)node * 32 + lane);
    float w0 = dd * dd;
    float4 acc = make_float4(v0.x * w0, v0.y * w0, v0.z * w0, v0.w * w0);

    int start = g_rowptr[node];
    int cnt   = g_deg[node];

    for (int base = 0; base < cnt; base += 32) {
        int n = cnt - base; if (n > 32) n = 32;
        int s = 0; float nm = 0.f;
        if (lane < n) {
            s  = __ldg(g_csrsrc + start + base + lane);
            nm = g_dinv[s] * dd;
        }
#pragma unroll 4
        for (int j = 0; j < n; j++) {
            int   sj = __shfl_sync(0xffffffffu, s,  j);
            float nj = __shfl_sync(0xffffffffu, nm, j);
            float4 v = __ldg(h + (size_t)sj * 32 + lane);
            acc.x += v.x * nj; acc.y += v.y * nj;
            acc.z += v.z * nj; acc.w += v.w * nj;
        }
    }

    int c = lane << 2;
    acc.x += __ldg(b2 + c + 0);
    acc.y += __ldg(b2 + c + 1);
    acc.z += __ldg(b2 + c + 2);
    acc.w += __ldg(b2 + c + 3);
    outh[(size_t)node * 32 + lane] = acc;

    float p[7];
#pragma unroll
    for (int j = 0; j < 4; j++) {
        p[j] = acc.x * __ldg(Wh1 + (c + 0) * 4 + j)
             + acc.y * __ldg(Wh1 + (c + 1) * 4 + j)
             + acc.z * __ldg(Wh1 + (c + 2) * 4 + j)
             + acc.w * __ldg(Wh1 + (c + 3) * 4 + j);
    }
#pragma unroll
    for (int j = 0; j < 3; j++) {
        p[4 + j] = acc.x * __ldg(Wh2 + (c + 0) * 3 + j)
                 + acc.y * __ldg(Wh2 + (c + 1) * 3 + j)
                 + acc.z * __ldg(Wh2 + (c + 2) * 3 + j)
                 + acc.w * __ldg(Wh2 + (c + 3) * 3 + j);
    }
#pragma unroll
    for (int j = 0; j < 7; j++) {
#pragma unroll
        for (int off = 16; off > 0; off >>= 1)
            p[j] += __shfl_xor_sync(0xffffffffu, p[j], off);
    }
    if (lane == 0) {
#pragma unroll
        for (int j = 0; j < 4; j++) out1[(size_t)node * 4 + j] = p[j] + __ldg(bh1 + j);
#pragma unroll
        for (int j = 0; j < 3; j++) out2[(size_t)node * 3 + j] = p[4 + j] + __ldg(bh2 + j);
    }
}

// ---------------------------------------------------------------- launch
extern "C" void kernel_launch(void* const* d_in, const int* in_sizes, int n_in,
                              void* d_out, int out_size)
{
    const float* x   = (const float*)d_in[0];
    const int*   ei  = (const int*)d_in[1];        // [2, E]
    const float* W1  = (const float*)d_in[2];
    const float* b1  = (const float*)d_in[3];
    const float* W2  = (const float*)d_in[4];
    const float* b2  = (const float*)d_in[5];
    const float* Wh1 = (const float*)d_in[6];
    const float* bh1 = (const float*)d_in[7];
    const float* Wh2 = (const float*)d_in[8];
    const float* bh2 = (const float*)d_in[9];

    const int* src = ei;
    const int* dst = ei + N_EDGES;

    float* out  = (float*)d_out;
    float* out1 = out;                                    // [N, 4]
    float* out2 = out + (size_t)N_NODES * 4;              // [N, 3]
    float4* outh = (float4*)(out + (size_t)N_NODES * 7);  // [N, 128]

    float* B0;  cudaGetSymbolAddress((void**)&B0, g_buf0);
    float* B1;  cudaGetSymbolAddress((void**)&B1, g_buf1);

    const int T = 256;
    int gNodes = (N_NODES + T - 1) / T;
    int gEdges = (N_EDGES + T - 1) / T;
    int gWarpN = (N_NODES * 32 + T - 1) / T;
    int gGemm  = (N_NODES + 127) / 128;

    // CSR-by-dst build + normalization
    zero_kernel<<<gNodes, T>>>();
    count_deg_kernel<<<gEdges, T>>>(dst);
    compute_dinv_kernel<<<gNodes, T>>>();
    scan_local_kernel<<<NB_SCAN, T>>>();
    scan_block_kernel<<<1, T>>>();
    scan_add_kernel<<<gNodes, T>>>();
    fill_csr_kernel<<<gEdges, T>>>(src, dst);

    // Layer 1: h1 = x @ W1 -> B0 ; agg+bias+relu -> B1
    gemm_bf16x3<<<gGemm, T>>>(x, W1, B0, N_NODES, F_IN);
    gather_relu_kernel<<<gWarpN, T>>>((const float4*)B0, (float4*)B1, b1);

    // Layer 2: h2 = h1r @ W2 -> B0 ; fused gather + heads
    gemm_bf16x3<<<gGemm, T>>>(B1, W2, B0, N_NODES, HDIM);
    gather_final_kernel<<<gWarpN, T>>>((const float4*)B0, b2, Wh1, bh1, Wh2, bh2,
                                       out1, out2, outh);

    (void)in_sizes; (void)n_in; (void)out_size;
}

// round 7
// speedup vs baseline: 3.1765x; 1.0681x over previous
#include <cuda_runtime.h>
#include <cuda_bf16.h>

#define N_NODES 50000
#define N_EDGES 800000
#define F_IN    256
#define HDIM    128
#define NB_SCAN ((N_NODES + 255) / 256)   // 196

// Scratch (device globals)
__device__ float g_buf0[N_NODES * HDIM];
__device__ float g_buf1[N_NODES * HDIM];
__device__ int   g_deg[N_NODES];
__device__ int   g_rowptr[N_NODES];
__device__ int   g_cursor[N_NODES];
__device__ int   g_csrsrc[N_EDGES];
__device__ float g_dinv[N_NODES];
__device__ int   g_bsum[256];

// Side stream + fork/join events, created once at static init (before any
// harness memory checkpoint; no device allocation inside kernel_launch).
static cudaStream_t g_side = nullptr;
static cudaEvent_t  g_ev_fork = nullptr, g_ev_join = nullptr;
namespace {
struct StreamInit {
    StreamInit() {
        cudaStreamCreateWithFlags(&g_side, cudaStreamNonBlocking);
        cudaEventCreateWithFlags(&g_ev_fork, cudaEventDisableTiming);
        cudaEventCreateWithFlags(&g_ev_join, cudaEventDisableTiming);
    }
};
static StreamInit g_stream_init;
}

// ---------------------------------------------------------------- degree
__global__ void zero_kernel() {
    int i = blockIdx.x * blockDim.x + threadIdx.x;
    if (i < N_NODES) { g_deg[i] = 0; g_cursor[i] = 0; }
}

__global__ void count_deg_kernel(const int* __restrict__ dst) {
    int i = blockIdx.x * blockDim.x + threadIdx.x;
    if (i < N_EDGES) atomicAdd(&g_deg[dst[i]], 1);
}

// ------------------------------------------------- 3-phase exclusive scan
// Phase 1 also computes dinv (reads deg anyway).
__global__ void __launch_bounds__(256) scan_local_kernel() {
    __shared__ int wsum[8];
    int tid = threadIdx.x, lane = tid & 31, wid = tid >> 5;
    int i = blockIdx.x * 256 + tid;
    int v = (i < N_NODES) ? g_deg[i] : 0;
    if (i < N_NODES) g_dinv[i] = rsqrtf((float)(v + 1));
    int incl = v;
#pragma unroll
    for (int off = 1; off < 32; off <<= 1) {
        int t = __shfl_up_sync(0xffffffffu, incl, off);
        if (lane >= off) incl += t;
    }
    if (lane == 31) wsum[wid] = incl;
    __syncthreads();
    if (wid == 0 && lane < 8) {
        int w = wsum[lane];
#pragma unroll
        for (int off = 1; off < 8; off <<= 1) {
            int t = __shfl_up_sync(0xffu, w, off);
            if (lane >= off) w += t;
        }
        wsum[lane] = w;
    }
    __syncthreads();
    int excl = incl - v + (wid ? wsum[wid - 1] : 0);
    if (i < N_NODES) g_rowptr[i] = excl;
    if (tid == 255) g_bsum[blockIdx.x] = wsum[7];
}

__global__ void __launch_bounds__(256) scan_block_kernel() {
    __shared__ int wsum[8];
    int tid = threadIdx.x, lane = tid & 31, wid = tid >> 5;
    int v = (tid < NB_SCAN) ? g_bsum[tid] : 0;
    int incl = v;
#pragma unroll
    for (int off = 1; off < 32; off <<= 1) {
        int t = __shfl_up_sync(0xffffffffu, incl, off);
        if (lane >= off) incl += t;
    }
    if (lane == 31) wsum[wid] = incl;
    __syncthreads();
    if (wid == 0 && lane < 8) {
        int w = wsum[lane];
#pragma unroll
        for (int off = 1; off < 8; off <<= 1) {
            int t = __shfl_up_sync(0xffu, w, off);
            if (lane >= off) w += t;
        }
        wsum[lane] = w;
    }
    __syncthreads();
    int excl = incl - v + (wid ? wsum[wid - 1] : 0);
    if (tid < NB_SCAN) g_bsum[tid] = excl;
}

__global__ void scan_add_kernel() {
    int i = blockIdx.x * blockDim.x + threadIdx.x;
    if (i < N_NODES) g_rowptr[i] += g_bsum[i >> 8];
}

__global__ void fill_csr_kernel(const int* __restrict__ src,
                                const int* __restrict__ dst) {
    int i = blockIdx.x * blockDim.x + threadIdx.x;
    if (i < N_EDGES) {
        int d = dst[i];
        int pos = g_rowptr[d] + atomicAdd(&g_cursor[d], 1);
        g_csrsrc[pos] = src[i];
    }
}

// ---------------------------------------------------------------- MMA GEMM
// C[M,128] = A[M,K] @ B[K,128] fp32, via bf16 2-split (3 MMAs per tile):
// A = Ah + Al, B = Bh + Bl ;  C ≈ Ah*Bh + Ah*Bl + Al*Bh  (error ~2^-16)

__device__ __forceinline__ void ldsm4(unsigned& r0, unsigned& r1,
                                      unsigned& r2, unsigned& r3,
                                      const void* p) {
    unsigned a = (unsigned)__cvta_generic_to_shared(p);
    asm volatile("ldmatrix.sync.aligned.m8n8.x4.shared.b16 {%0,%1,%2,%3}, [%4];"
                 : "=r"(r0), "=r"(r1), "=r"(r2), "=r"(r3) : "r"(a));
}

__device__ __forceinline__ void ldsm4t(unsigned& r0, unsigned& r1,
                                       unsigned& r2, unsigned& r3,
                                       const void* p) {
    unsigned a = (unsigned)__cvta_generic_to_shared(p);
    asm volatile("ldmatrix.sync.aligned.m8n8.x4.trans.shared.b16 {%0,%1,%2,%3}, [%4];"
                 : "=r"(r0), "=r"(r1), "=r"(r2), "=r"(r3) : "r"(a));
}

__device__ __forceinline__ void mma16816(float* d, const unsigned* a,
                                         unsigned b0, unsigned b1) {
    asm volatile(
        "mma.sync.aligned.m16n8k16.row.col.f32.bf16.bf16.f32 "
        "{%0,%1,%2,%3}, {%4,%5,%6,%7}, {%8,%9}, {%0,%1,%2,%3};\n"
        : "+f"(d[0]), "+f"(d[1]), "+f"(d[2]), "+f"(d[3])
        : "r"(a[0]), "r"(a[1]), "r"(a[2]), "r"(a[3]), "r"(b0), "r"(b1));
}

__device__ __forceinline__ void split2(float x, float y,
                                       __nv_bfloat162& hi, __nv_bfloat162& lo) {
    __nv_bfloat16 hx = __float2bfloat16(x);
    __nv_bfloat16 hy = __float2bfloat16(y);
    __nv_bfloat16 lx = __float2bfloat16(x - __bfloat162float(hx));
    __nv_bfloat16 ly = __float2bfloat16(y - __bfloat162float(hy));
    hi = __halves2bfloat162(hx, hy);
    lo = __halves2bfloat162(lx, ly);
}

#define SA_LD 24   // 16 + 8 pad
#define SB_LD 136  // 128 + 8 pad

__global__ void __launch_bounds__(256) gemm_bf16x3(
    const float* __restrict__ A, const float* __restrict__ B,
    float* __restrict__ C, int M, int K)
{
    __shared__ __align__(16) __nv_bfloat16 sAh[2][128][SA_LD];
    __shared__ __align__(16) __nv_bfloat16 sAl[2][128][SA_LD];
    __shared__ __align__(16) __nv_bfloat16 sBh[2][16][SB_LD];
    __shared__ __align__(16) __nv_bfloat16 sBl[2][16][SB_LD];

    const int tid  = threadIdx.x;
    const int lane = tid & 31;
    const int wid  = tid >> 5;
    const int bm   = blockIdx.x * 128;

    const int wm = (wid >> 1) * 32;
    const int wn = (wid & 1) * 64;

    const int arow = tid >> 1;
    const int acg  = (tid & 1) * 8;
    const int brow = tid >> 4;
    const int bcg  = (tid & 15) * 8;

    const bool avalid = (bm + arow) < M;

    const int a_r = ((lane >> 3) & 1) * 8 + (lane & 7);
    const int a_c = (lane >> 4) * 8;
    const int b_k = ((lane >> 3) & 1) * 8 + (lane & 7);
    const int b_n = (lane >> 4) * 8;

    float acc[2][8][4];
#pragma unroll
    for (int i = 0; i < 2; i++)
#pragma unroll
        for (int j = 0; j < 8; j++)
#pragma unroll
            for (int q = 0; q < 4; q++) acc[i][j][q] = 0.0f;

    const int nt = K >> 4;

    {
        float4 a0 = make_float4(0.f,0.f,0.f,0.f), a1 = a0;
        if (avalid) {
            a0 = *(const float4*)(A + (size_t)(bm + arow) * K + acg);
            a1 = *(const float4*)(A + (size_t)(bm + arow) * K + acg + 4);
        }
        float4 b0 = *(const float4*)(B + (size_t)brow * 128 + bcg);
        float4 b1 = *(const float4*)(B + (size_t)brow * 128 + bcg + 4);
        __nv_bfloat162 h, l;
        split2(a0.x, a0.y, h, l);
        *(__nv_bfloat162*)&sAh[0][arow][acg+0] = h; *(__nv_bfloat162*)&sAl[0][arow][acg+0] = l;
        split2(a0.z, a0.w, h, l);
        *(__nv_bfloat162*)&sAh[0][arow][acg+2] = h; *(__nv_bfloat162*)&sAl[0][arow][acg+2] = l;
        split2(a1.x, a1.y, h, l);
        *(__nv_bfloat162*)&sAh[0][arow][acg+4] = h; *(__nv_bfloat162*)&sAl[0][arow][acg+4] = l;
        split2(a1.z, a1.w, h, l);
        *(__nv_bfloat162*)&sAh[0][arow][acg+6] = h; *(__nv_bfloat162*)&sAl[0][arow][acg+6] = l;
        split2(b0.x, b0.y, h, l);
        *(__nv_bfloat162*)&sBh[0][brow][bcg+0] = h; *(__nv_bfloat162*)&sBl[0][brow][bcg+0] = l;
        split2(b0.z, b0.w, h, l);
        *(__nv_bfloat162*)&sBh[0][brow][bcg+2] = h; *(__nv_bfloat162*)&sBl[0][brow][bcg+2] = l;
        split2(b1.x, b1.y, h, l);
        *(__nv_bfloat162*)&sBh[0][brow][bcg+4] = h; *(__nv_bfloat162*)&sBl[0][brow][bcg+4] = l;
        split2(b1.z, b1.w, h, l);
        *(__nv_bfloat162*)&sBh[0][brow][bcg+6] = h; *(__nv_bfloat162*)&sBl[0][brow][bcg+6] = l;
    }
    __syncthreads();

    for (int t = 0; t < nt; t++) {
        const int cur = t & 1;

        float4 a0, a1, b0, b1;
        const bool more = (t + 1) < nt;
        if (more) {
            int k0 = (t + 1) << 4;
            a0 = make_float4(0.f,0.f,0.f,0.f); a1 = a0;
            if (avalid) {
                a0 = *(const float4*)(A + (size_t)(bm + arow) * K + k0 + acg);
                a1 = *(const float4*)(A + (size_t)(bm + arow) * K + k0 + acg + 4);
            }
            b0 = *(const float4*)(B + (size_t)(k0 + brow) * 128 + bcg);
            b1 = *(const float4*)(B + (size_t)(k0 + brow) * 128 + bcg + 4);
        }

        unsigned ah[2][4], al[2][4];
#pragma unroll
        for (int tm = 0; tm < 2; tm++) {
            ldsm4(ah[tm][0], ah[tm][1], ah[tm][2], ah[tm][3],
                  &sAh[cur][wm + tm*16 + a_r][a_c]);
            ldsm4(al[tm][0], al[tm][1], al[tm][2], al[tm][3],
                  &sAl[cur][wm + tm*16 + a_r][a_c]);
        }
#pragma unroll
        for (int np = 0; np < 4; np++) {
            unsigned bh[4], bl[4];
            int n0 = wn + np * 16;
            ldsm4t(bh[0], bh[1], bh[2], bh[3], &sBh[cur][b_k][n0 + b_n]);
            ldsm4t(bl[0], bl[1], bl[2], bl[3], &sBl[cur][b_k][n0 + b_n]);
#pragma unroll
            for (int tm = 0; tm < 2; tm++) {
#pragma unroll
                for (int h = 0; h < 2; h++) {
                    float* d = acc[tm][np * 2 + h];
                    mma16816(d, ah[tm], bh[2*h], bh[2*h + 1]);
                    mma16816(d, ah[tm], bl[2*h], bl[2*h + 1]);
                    mma16816(d, al[tm], bh[2*h], bh[2*h + 1]);
                }
            }
        }

        if (more) {
            const int nxt = cur ^ 1;
            __nv_bfloat162 h, l;
            split2(a0.x, a0.y, h, l);
            *(__nv_bfloat162*)&sAh[nxt][arow][acg+0] = h; *(__nv_bfloat162*)&sAl[nxt][arow][acg+0] = l;
            split2(a0.z, a0.w, h, l);
            *(__nv_bfloat162*)&sAh[nxt][arow][acg+2] = h; *(__nv_bfloat162*)&sAl[nxt][arow][acg+2] = l;
            split2(a1.x, a1.y, h, l);
            *(__nv_bfloat162*)&sAh[nxt][arow][acg+4] = h; *(__nv_bfloat162*)&sAl[nxt][arow][acg+4] = l;
            split2(a1.z, a1.w, h, l);
            *(__nv_bfloat162*)&sAh[nxt][arow][acg+6] = h; *(__nv_bfloat162*)&sAl[nxt][arow][acg+6] = l;
            split2(b0.x, b0.y, h, l);
            *(__nv_bfloat162*)&sBh[nxt][brow][bcg+0] = h; *(__nv_bfloat162*)&sBl[nxt][brow][bcg+0] = l;
            split2(b0.z, b0.w, h, l);
            *(__nv_bfloat162*)&sBh[nxt][brow][bcg+2] = h; *(__nv_bfloat162*)&sBl[nxt][brow][bcg+2] = l;
            split2(b1.x, b1.y, h, l);
            *(__nv_bfloat162*)&sBh[nxt][brow][bcg+4] = h; *(__nv_bfloat162*)&sBl[nxt][brow][bcg+4] = l;
            split2(b1.z, b1.w, h, l);
            *(__nv_bfloat162*)&sBh[nxt][brow][bcg+6] = h; *(__nv_bfloat162*)&sBl[nxt][brow][bcg+6] = l;
        }
        __syncthreads();
    }

    const int g = lane >> 2;
    const int tq = lane & 3;
#pragma unroll
    for (int tm = 0; tm < 2; tm++) {
        int r0 = bm + wm + tm * 16 + g;
        int r1 = r0 + 8;
#pragma unroll
        for (int n8 = 0; n8 < 8; n8++) {
            int col = wn + n8 * 8 + tq * 2;
            float* d = acc[tm][n8];
            if (r0 < M) *(float2*)(C + (size_t)r0 * 128 + col) = make_float2(d[0], d[1]);
            if (r1 < M) *(float2*)(C + (size_t)r1 * 128 + col) = make_float2(d[2], d[3]);
        }
    }
}

// ---------------------------------------------------------------- gather L1
__global__ void gather_relu_kernel(const float4* __restrict__ h,
                                   float4* __restrict__ out,
                                   const float* __restrict__ bias)
{
    int node = (blockIdx.x * blockDim.x + threadIdx.x) >> 5;
    if (node >= N_NODES) return;
    int lane = threadIdx.x & 31;

    float dd = g_dinv[node];
    float4 v0 = __ldg(h + (size_t)node * 32 + lane);
    float w0 = dd * dd;
    float4 acc = make_float4(v0.x * w0, v0.y * w0, v0.z * w0, v0.w * w0);

    int start = g_rowptr[node];
    int cnt   = g_deg[node];

    for (int base = 0; base < cnt; base += 32) {
        int n = cnt - base; if (n > 32) n = 32;
        int s = 0; float nm = 0.f;
        if (lane < n) {
            s  = __ldg(g_csrsrc + start + base + lane);
            nm = g_dinv[s] * dd;
        }
#pragma unroll 4
        for (int j = 0; j < n; j++) {
            int   sj = __shfl_sync(0xffffffffu, s,  j);
            float nj = __shfl_sync(0xffffffffu, nm, j);
            float4 v = __ldg(h + (size_t)sj * 32 + lane);
            acc.x += v.x * nj; acc.y += v.y * nj;
            acc.z += v.z * nj; acc.w += v.w * nj;
        }
    }

    int c = lane << 2;
    acc.x = fmaxf(acc.x + __ldg(bias + c + 0), 0.f);
    acc.y = fmaxf(acc.y + __ldg(bias + c + 1), 0.f);
    acc.z = fmaxf(acc.z + __ldg(bias + c + 2), 0.f);
    acc.w = fmaxf(acc.w + __ldg(bias + c + 3), 0.f);
    out[(size_t)node * 32 + lane] = acc;
}

// ------------------------------------------- gather L2 + finalize (fused)
__global__ void gather_final_kernel(const float4* __restrict__ h,
                                    const float* __restrict__ b2,
                                    const float* __restrict__ Wh1,
                                    const float* __restrict__ bh1,
                                    const float* __restrict__ Wh2,
                                    const float* __restrict__ bh2,
                                    float* __restrict__ out1,
                                    float* __restrict__ out2,
                                    float4* __restrict__ outh)
{
    int node = (blockIdx.x * blockDim.x + threadIdx.x) >> 5;
    if (node >= N_NODES) return;
    int lane = threadIdx.x & 31;

    float dd = g_dinv[node];
    float4 v0 = __ldg(h + (size_t)node * 32 + lane);
    float w0 = dd * dd;
    float4 acc = make_float4(v0.x * w0, v0.y * w0, v0.z * w0, v0.w * w0);

    int start = g_rowptr[node];
    int cnt   = g_deg[node];

    for (int base = 0; base < cnt; base += 32) {
        int n = cnt - base; if (n > 32) n = 32;
        int s = 0; float nm = 0.f;
        if (lane < n) {
            s  = __ldg(g_csrsrc + start + base + lane);
            nm = g_dinv[s] * dd;
        }
#pragma unroll 4
        for (int j = 0; j < n; j++) {
            int   sj = __shfl_sync(0xffffffffu, s,  j);
            float nj = __shfl_sync(0xffffffffu, nm, j);
            float4 v = __ldg(h + (size_t)sj * 32 + lane);
            acc.x += v.x * nj; acc.y += v.y * nj;
            acc.z += v.z * nj; acc.w += v.w * nj;
        }
    }

    int c = lane << 2;
    acc.x += __ldg(b2 + c + 0);
    acc.y += __ldg(b2 + c + 1);
    acc.z += __ldg(b2 + c + 2);
    acc.w += __ldg(b2 + c + 3);
    outh[(size_t)node * 32 + lane] = acc;

    float p[7];
#pragma unroll
    for (int j = 0; j < 4; j++) {
        p[j] = acc.x * __ldg(Wh1 + (c + 0) * 4 + j)
             + acc.y * __ldg(Wh1 + (c + 1) * 4 + j)
             + acc.z * __ldg(Wh1 + (c + 2) * 4 + j)
             + acc.w * __ldg(Wh1 + (c + 3) * 4 + j);
    }
#pragma unroll
    for (int j = 0; j < 3; j++) {
        p[4 + j] = acc.x * __ldg(Wh2 + (c + 0) * 3 + j)
                 + acc.y * __ldg(Wh2 + (c + 1) * 3 + j)
                 + acc.z * __ldg(Wh2 + (c + 2) * 3 + j)
                 + acc.w * __ldg(Wh2 + (c + 3) * 3 + j);
    }
#pragma unroll
    for (int j = 0; j < 7; j++) {
#pragma unroll
        for (int off = 16; off > 0; off >>= 1)
            p[j] += __shfl_xor_sync(0xffffffffu, p[j], off);
    }
    if (lane == 0) {
#pragma unroll
        for (int j = 0; j < 4; j++) out1[(size_t)node * 4 + j] = p[j] + __ldg(bh1 + j);
#pragma unroll
        for (int j = 0; j < 3; j++) out2[(size_t)node * 3 + j] = p[4 + j] + __ldg(bh2 + j);
    }
}

// ---------------------------------------------------------------- launch
extern "C" void kernel_launch(void* const* d_in, const int* in_sizes, int n_in,
                              void* d_out, int out_size)
{
    const float* x   = (const float*)d_in[0];
    const int*   ei  = (const int*)d_in[1];        // [2, E]
    const float* W1  = (const float*)d_in[2];
    const float* b1  = (const float*)d_in[3];
    const float* W2  = (const float*)d_in[4];
    const float* b2  = (const float*)d_in[5];
    const float* Wh1 = (const float*)d_in[6];
    const float* bh1 = (const float*)d_in[7];
    const float* Wh2 = (const float*)d_in[8];
    const float* bh2 = (const float*)d_in[9];

    const int* src = ei;
    const int* dst = ei + N_EDGES;

    float* out  = (float*)d_out;
    float* out1 = out;                                    // [N, 4]
    float* out2 = out + (size_t)N_NODES * 4;              // [N, 3]
    float4* outh = (float4*)(out + (size_t)N_NODES * 7);  // [N, 128]

    float* B0;  cudaGetSymbolAddress((void**)&B0, g_buf0);
    float* B1;  cudaGetSymbolAddress((void**)&B1, g_buf1);

    const int T = 256;
    int gNodes = (N_NODES + T - 1) / T;
    int gEdges = (N_EDGES + T - 1) / T;
    int gWarpN = (N_NODES * 32 + T - 1) / T;
    int gGemm  = (N_NODES + 127) / 128;

    // Fork: CSR build on side stream, GEMM1 on main stream (independent).
    cudaEventRecord(g_ev_fork, 0);
    cudaStreamWaitEvent(g_side, g_ev_fork, 0);

    // Side stream: CSR-by-dst build + normalization
    zero_kernel<<<gNodes, T, 0, g_side>>>();
    count_deg_kernel<<<gEdges, T, 0, g_side>>>(dst);
    scan_local_kernel<<<NB_SCAN, T, 0, g_side>>>();   // also computes dinv
    scan_block_kernel<<<1, T, 0, g_side>>>();
    scan_add_kernel<<<gNodes, T, 0, g_side>>>();
    fill_csr_kernel<<<gEdges, T, 0, g_side>>>(src, dst);
    cudaEventRecord(g_ev_join, g_side);

    // Main stream: Layer 1 GEMM (needs only x, W1)
    gemm_bf16x3<<<gGemm, T>>>(x, W1, B0, N_NODES, F_IN);

    // Join: gather needs both GEMM1 output and CSR
    cudaStreamWaitEvent(0, g_ev_join, 0);
    gather_relu_kernel<<<gWarpN, T>>>((const float4*)B0, (float4*)B1, b1);

    // Layer 2: h2 = h1r @ W2 -> B0 ; fused gather + heads
    gemm_bf16x3<<<gGemm, T>>>(B1, W2, B0, N_NODES, HDIM);
    gather_final_kernel<<<gWarpN, T>>>((const float4*)B0, b2, Wh1, bh1, Wh2, bh2,
                                       out1, out2, outh);

    (void)in_sizes; (void)n_in; (void)out_size;
}